// round 4
// baseline (speedup 1.0000x reference)
#include <cuda_runtime.h>
#include <cstdint>

#define BS    8
#define CDIM  256
#define SP    16384            // 16*32*32 spatial per batch
#define NTOK  (BS * SP)        // 131072
#define NCODE 1024
#define NQ    (BS * CDIM * SP) // 33554432

#define TM 64                  // tokens per block
#define TN 64                  // codes per tile
#define KC 64                  // k-chunk
#define CP 68                  // padded cs row

__device__ float g_cnorm[NCODE];
__device__ float g_znorm[NTOK];
__device__ int   g_idx[NTOK];

// ---------------------------------------------------------------------------
// ||c_j||^2 : bit-exact XLA:CPU emulation — scalar sequential ascending k,
// separate rounded mul and add (reduce over fl(c*c)).
// ---------------------------------------------------------------------------
__global__ void cnorm_kernel(const float* __restrict__ cb) {
    int r = blockIdx.x * 256 + threadIdx.x;   // 4 blocks x 256 = 1024 rows
    const float* row = cb + (size_t)r * CDIM;
    float s = 0.f;
#pragma unroll 8
    for (int k = 0; k < CDIM; ++k) {
        float v = row[k];
        s = __fadd_rn(s, __fmul_rn(v, v));
    }
    g_cnorm[r] = s;
}

// ---------------------------------------------------------------------------
// ||z_n||^2 : same sequential emulation. One thread per token; k-stride SP so
// loads are coalesced across adjacent tokens.
// ---------------------------------------------------------------------------
__global__ void znorm_kernel(const float* __restrict__ z) {
    int n = blockIdx.x * 256 + threadIdx.x;   // NTOK/256 blocks
    int b = n / SP, s0 = n % SP;
    const float* p = z + (size_t)b * CDIM * SP + s0;
    float s = 0.f;
#pragma unroll 8
    for (int k = 0; k < CDIM; ++k) {
        float v = p[(size_t)k * SP];
        s = __fadd_rn(s, __fmul_rn(v, v));
    }
    g_znorm[n] = s;
}

// ---------------------------------------------------------------------------
// argmin GEMM, reference-rounding emulation:
//   dot    = single FFMA chain over k=0..255 ascending  (Eigen gebp order)
//   d2     = fl( fl(znorm + (-2*dot)) + cnorm )          ((A-B)+C epilogue)
//   argmin = strict <, ascending index (first occurrence on ties)
// block = 64 tokens x 1024 codes, 256 threads (16x16), 4x4 register tile,
// z tile staged transposed once, codebook double-buffered.
// ---------------------------------------------------------------------------
__global__ __launch_bounds__(256, 2) void argmin_kernel(
    const float* __restrict__ z, const float* __restrict__ cb,
    float* __restrict__ oidx)
{
    extern __shared__ float smem[];
    float* zs  = smem;                     // [CDIM][TM]   = 16384 f
    float* cs  = smem + CDIM * TM;         // [2][KC][CP]  =  8704 f
    float* cns = cs + 2 * KC * CP;         // [NCODE]      =  1024 f

    const int tid = threadIdx.x;
    const int n0  = blockIdx.x * TM;
    const int b   = n0 / SP;
    const int s0  = n0 % SP;
    const float* zbase = z + (size_t)b * CDIM * SP + s0;

    // stage z tile transposed: zs[k][tok]
    for (int i = tid; i < CDIM * TM; i += 256) {
        int k = i >> 6, tok = i & 63;
        zs[i] = zbase[(size_t)k * SP + tok];
    }
    for (int i = tid; i < NCODE; i += 256) cns[i] = g_cnorm[i];

    // preload chunk 0 (code tile 0, kc 0): cs[k][jj] = cb[jj][k]
    for (int i = tid; i < TN * KC; i += 256) {
        int jj = i >> 6, k = i & 63;
        cs[k * CP + jj] = cb[jj * CDIM + k];
    }

    const int ty = tid >> 4, tx = tid & 15;
    const int ty4 = ty * 4, tx4 = tx * 4;

    // per-token znorm (4 tokens owned by this thread row)
    float zn[4];
#pragma unroll
    for (int i = 0; i < 4; ++i) zn[i] = g_znorm[n0 + ty4 + i];

    float acc[4][4];
#pragma unroll
    for (int i = 0; i < 4; i++)
#pragma unroll
        for (int j = 0; j < 4; j++) acc[i][j] = 0.f;

    float bestv[4];
    int   besti[4];
#pragma unroll
    for (int i = 0; i < 4; i++) { bestv[i] = 3.4e38f; besti[i] = 0; }

    const int NSTEP = (NCODE / TN) * (CDIM / KC);  // 64
    for (int step = 0; step < NSTEP; ++step) {
        __syncthreads();
        const float* csb = cs + (step & 1) * (KC * CP);
        const float* za  = zs + ((step & 3) * KC) * TM + ty4;

#pragma unroll 16
        for (int kk = 0; kk < KC; ++kk) {
            float4 a  = *(const float4*)(za  + kk * TM);
            float4 bv = *(const float4*)(csb + kk * CP + tx4);
            acc[0][0] = __fmaf_rn(a.x, bv.x, acc[0][0]);
            acc[0][1] = __fmaf_rn(a.x, bv.y, acc[0][1]);
            acc[0][2] = __fmaf_rn(a.x, bv.z, acc[0][2]);
            acc[0][3] = __fmaf_rn(a.x, bv.w, acc[0][3]);
            acc[1][0] = __fmaf_rn(a.y, bv.x, acc[1][0]);
            acc[1][1] = __fmaf_rn(a.y, bv.y, acc[1][1]);
            acc[1][2] = __fmaf_rn(a.y, bv.z, acc[1][2]);
            acc[1][3] = __fmaf_rn(a.y, bv.w, acc[1][3]);
            acc[2][0] = __fmaf_rn(a.z, bv.x, acc[2][0]);
            acc[2][1] = __fmaf_rn(a.z, bv.y, acc[2][1]);
            acc[2][2] = __fmaf_rn(a.z, bv.z, acc[2][2]);
            acc[2][3] = __fmaf_rn(a.z, bv.w, acc[2][3]);
            acc[3][0] = __fmaf_rn(a.w, bv.x, acc[3][0]);
            acc[3][1] = __fmaf_rn(a.w, bv.y, acc[3][1]);
            acc[3][2] = __fmaf_rn(a.w, bv.z, acc[3][2]);
            acc[3][3] = __fmaf_rn(a.w, bv.w, acc[3][3]);
        }

        // prefetch next chunk into the other buffer
        if (step + 1 < NSTEP) {
            int ns = step + 1;
            int jt = ns >> 2, kc = ns & 3;
            const float* src = cb + (size_t)(jt * TN) * CDIM + kc * KC;
            float* dst = cs + (ns & 1) * (KC * CP);
            for (int i = tid; i < TN * KC; i += 256) {
                int jj = i >> 6, k = i & 63;
                dst[k * CP + jj] = src[(size_t)jj * CDIM + k];
            }
        }

        // finished K=256 for this code tile -> reference-rounded score + argmin
        if ((step & 3) == 3) {
            int j0 = (step >> 2) * TN + tx4;
#pragma unroll
            for (int j = 0; j < 4; ++j) {
                float cn = cns[j0 + j];
#pragma unroll
                for (int i = 0; i < 4; ++i) {
                    float t1 = __fadd_rn(zn[i], __fmul_rn(acc[i][j], -2.0f));
                    float sc = __fadd_rn(t1, cn);
                    if (sc < bestv[i]) { bestv[i] = sc; besti[i] = j0 + j; }
                    acc[i][j] = 0.f;
                }
            }
        }
    }

    // reduce over the 16 tx lanes; lower index wins ties
#pragma unroll
    for (int o = 8; o; o >>= 1) {
#pragma unroll
        for (int i = 0; i < 4; ++i) {
            float ov = __shfl_xor_sync(0xffffffffu, bestv[i], o);
            int   oi = __shfl_xor_sync(0xffffffffu, besti[i], o);
            if (ov < bestv[i] || (ov == bestv[i] && oi < besti[i])) {
                bestv[i] = ov; besti[i] = oi;
            }
        }
    }
    if (tx == 0) {
#pragma unroll
        for (int i = 0; i < 4; ++i) {
            int n = n0 + ty4 + i;
            g_idx[n] = besti[i];
            if (oidx) oidx[n] = (float)besti[i];
        }
    }
}

// ---------------------------------------------------------------------------
// gather + transpose writer: 64 tokens x 256 channels per block.
// st = z + (q - z) with explicit sub/add rounding (matches reference).
// ---------------------------------------------------------------------------
#define P2 65
__global__ __launch_bounds__(256) void write_kernel(
    const float* __restrict__ cb, const float* __restrict__ z,
    float* __restrict__ outq, float* __restrict__ outst)
{
    extern __shared__ float sm[];
    float* tile = sm;                          // [CDIM][P2]
    int*   sidx = (int*)(sm + CDIM * P2);      // [64]

    const int tid = threadIdx.x;
    const int n0  = blockIdx.x * 64;
    const int b   = n0 / SP;
    const int s0  = n0 % SP;

    if (tid < 64) sidx[tid] = g_idx[n0 + tid];
    __syncthreads();

    const int c = tid;
#pragma unroll 8
    for (int tok = 0; tok < 64; ++tok) {
        tile[c * P2 + tok] = cb[(size_t)sidx[tok] * CDIM + c];
    }
    __syncthreads();

    const size_t base = (size_t)b * CDIM * SP + s0;
    for (int r = 0; r < 64; ++r) {
        int lin = r * 256 + tid;
        int cc  = lin >> 6, tok = lin & 63;
        size_t addr = base + (size_t)cc * SP + tok;
        float q  = tile[cc * P2 + tok];
        outq[addr] = q;
        if (outst) {
            float zv = z[addr];
            outst[addr] = __fadd_rn(zv, __fadd_rn(q, -zv));
        }
    }
}

// ---------------------------------------------------------------------------
extern "C" void kernel_launch(void* const* d_in, const int* in_sizes, int n_in,
                              void* d_out, int out_size) {
    const float* z  = (const float*)d_in[0];
    const float* cb = (const float*)d_in[1];
    float* out = (float*)d_out;

    float* outq   = out;
    float* outst  = nullptr;
    float* outidx = nullptr;
    if (out_size >= 2 * NQ + NTOK)      { outst = out + NQ; outidx = out + 2 * (size_t)NQ; }
    else if (out_size >= 2 * NQ)        { outst = out + NQ; }
    else if (out_size >= NQ + NTOK)     { outidx = out + NQ; }

    int smemB = (CDIM * TM + 2 * KC * CP + NCODE) * (int)sizeof(float); // 104448
    int smemC = CDIM * P2 * (int)sizeof(float) + 64 * (int)sizeof(int); // 66816
    cudaFuncSetAttribute(argmin_kernel, cudaFuncAttributeMaxDynamicSharedMemorySize, smemB);
    cudaFuncSetAttribute(write_kernel,  cudaFuncAttributeMaxDynamicSharedMemorySize, smemC);

    cnorm_kernel<<<NCODE / 256, 256>>>(cb);
    znorm_kernel<<<NTOK / 256, 256>>>(z);
    argmin_kernel<<<NTOK / TM, 256, smemB>>>(z, cb, outidx);
    write_kernel<<<NTOK / 64, 256, smemC>>>(cb, z, outq, outst);
}

// round 8
// speedup vs baseline: 2.2622x; 2.2622x over previous
#include <cuda_runtime.h>
#include <cuda_fp16.h>
#include <cstdint>

#define BS    8
#define CDIM  256
#define SP    16384            // 16*32*32 spatial per batch
#define NTOK  (BS * SP)        // 131072
#define NCODE 1024
#define NQ    (BS * CDIM * SP) // 33554432

#define MT     128             // tokens per screen block
#define ZP     264             // padded smem row stride (halves)
#define SCODES 64              // codes per stage
#define NSTAGE (NCODE / SCODES) // 16
#define MARGIN 1.5e-3f
#define MAXCAND 12

__device__ float  g_cnorm[NCODE];
__device__ int    g_idx[NTOK];
__device__ __half g_cbh[NCODE * CDIM];   // fp16 codebook, plain [code][k]

// ---------------- PTX helpers (sm_103-safe: no 'a' features) ---------------
#define CP_ASYNC16(dst, src) asm volatile("cp.async.cg.shared.global [%0], [%1], 16;" :: "r"(dst), "l"(src) : "memory")
#define CP_COMMIT()          asm volatile("cp.async.commit_group;" ::: "memory")
#define CP_WAIT0()           asm volatile("cp.async.wait_group 0;" ::: "memory")

__device__ __forceinline__ uint32_t smem_u32(const void* p) {
    uint32_t a;
    asm("{ .reg .u64 t; cvta.to.shared.u64 t, %1; cvt.u32.u64 %0, t; }" : "=r"(a) : "l"(p));
    return a;
}
__device__ __forceinline__ void mma16816(float4& c, const uint32_t* a, const uint32_t* b) {
    asm volatile("mma.sync.aligned.m16n8k16.row.col.f32.f16.f16.f32 "
        "{%0,%1,%2,%3}, {%4,%5,%6,%7}, {%8,%9}, {%0,%1,%2,%3};"
        : "+f"(c.x), "+f"(c.y), "+f"(c.z), "+f"(c.w)
        : "r"(a[0]), "r"(a[1]), "r"(a[2]), "r"(a[3]), "r"(b[0]), "r"(b[1]));
}
// order-preserving float<->uint for atomicMin
__device__ __forceinline__ uint32_t fenc(float f) {
    uint32_t u = __float_as_uint(f);
    return (u >> 31) ? ~u : (u | 0x80000000u);
}
__device__ __forceinline__ float fdec(uint32_t k) {
    uint32_t u = (k >> 31) ? (k & 0x7fffffffu) : ~k;
    return __uint_as_float(u);
}
__device__ __forceinline__ void ins3(float v, int j, float* bv, int* bi) {
    if (v < bv[2]) {
        if (v < bv[1]) {
            bv[2] = bv[1]; bi[2] = bi[1];
            if (v < bv[0]) { bv[1] = bv[0]; bi[1] = bi[0]; bv[0] = v; bi[0] = j; }
            else           { bv[1] = v;     bi[1] = j; }
        } else { bv[2] = v; bi[2] = j; }
    }
}

// ---------------------------------------------------------------------------
// ||c_j||^2 exact (scalar sequential ascending k — validated bit-exact in R4)
// ---------------------------------------------------------------------------
__global__ void cnorm_kernel(const float* __restrict__ cb) {
    int r = blockIdx.x * 256 + threadIdx.x;
    const float* row = cb + (size_t)r * CDIM;
    float s = 0.f;
#pragma unroll 8
    for (int k = 0; k < CDIM; ++k) { float v = row[k]; s = __fadd_rn(s, __fmul_rn(v, v)); }
    g_cnorm[r] = s;
}

// fp16 codebook conversion (plain layout)
__global__ void cbh_kernel(const float* __restrict__ cb) {
    int i = blockIdx.x * 256 + threadIdx.x;
    g_cbh[i] = __float2half_rn(cb[i]);
}

// ---------------------------------------------------------------------------
// HMMA screening + candidate select + exact rescore.
// 256 thr = 8 warps = 4 token-groups (32 tok) x 2 code-halves (32 codes/stage).
// Per warp per stage: m32 x n32, K=256 (16 k-steps), acc in registers.
// smem (146432 B): z tile [128][264]h | 2x cb stage [64][264]h | cns | cands
// ---------------------------------------------------------------------------
#define CB_BYTES (SCODES * ZP * 2)                 // 33792
#define SM_ZT    0
#define SM_CB    (MT * ZP * 2)                     // 67584
#define SM_CNS   (SM_CB + 2 * CB_BYTES)            // 135168
#define SM_MINK  (SM_CNS + NCODE * 4)              // 139264
#define SM_CCNT  (SM_MINK + MT * 4)                // 139776
#define SM_CAND  (SM_CCNT + MT * 4)                // 140288
#define SM_TOTAL (SM_CAND + MT * MAXCAND * 4)      // 146432

__global__ __launch_bounds__(256, 1)
void screen_kernel(const float* __restrict__ z, const float* __restrict__ cb,
                   float* __restrict__ oidx)
{
    extern __shared__ char smem[];
    __half* zt = (__half*)(smem + SM_ZT);
    float*  cns = (float*)(smem + SM_CNS);
    uint32_t* minkey = (uint32_t*)(smem + SM_MINK);
    int* candcnt = (int*)(smem + SM_CCNT);
    int* cand    = (int*)(smem + SM_CAND);

    const int tid = threadIdx.x;
    const int wid = tid >> 5, lane = tid & 31;
    const int tg = wid >> 1, ch = wid & 1;        // token group / code half
    const int r = lane >> 2, c2 = (lane & 3) * 2;

    const int n0 = blockIdx.x * MT;
    const int b  = n0 / SP, s0 = n0 % SP;
    const float* zbase = z + (size_t)b * CDIM * SP + s0;

    uint32_t cbu0 = smem_u32(smem + SM_CB);
    uint32_t cbu1 = cbu0 + CB_BYTES;

    // ---- prologue: z tile fp16 (padded), cns, mins, stage-0 cp.async ----
    for (int i = tid; i < MT * CDIM; i += 256) {
        int k = i >> 7, tok = i & (MT - 1);
        zt[tok * ZP + k] = __float2half_rn(zbase[(size_t)k * SP + tok]);
    }
    for (int i = tid; i < NCODE; i += 256) cns[i] = g_cnorm[i];
    if (tid < MT) { minkey[tid] = 0xFFFFFFFFu; candcnt[tid] = 0; }
    {
        const __half* src = g_cbh;     // stage 0: 64 codes x 256 halves
#pragma unroll
        for (int it = 0; it < 8; ++it) {
            int id = tid + it * 256;
            int cc = id >> 5, kc = (id & 31) * 8;
            CP_ASYNC16(cbu0 + (uint32_t)(cc * ZP + kc) * 2, src + cc * CDIM + kc);
        }
        CP_COMMIT();
    }
    CP_WAIT0();
    __syncthreads();

    float bv[4][3]; int bi[4][3];
#pragma unroll
    for (int s = 0; s < 4; ++s)
#pragma unroll
        for (int q = 0; q < 3; ++q) { bv[s][q] = 3.4e38f; bi[s][q] = 0; }

    for (int st = 0; st < NSTAGE; ++st) {
        // issue next stage loads into the other buffer
        if (st + 1 < NSTAGE) {
            const __half* src = g_cbh + (size_t)(st + 1) * SCODES * CDIM;
            uint32_t dstb = ((st + 1) & 1) ? cbu1 : cbu0;
#pragma unroll
            for (int it = 0; it < 8; ++it) {
                int id = tid + it * 256;
                int cc = id >> 5, kc = (id & 31) * 8;
                CP_ASYNC16(dstb + (uint32_t)(cc * ZP + kc) * 2, src + cc * CDIM + kc);
            }
            CP_COMMIT();
        }

        // ---- compute stage st on buffer st&1 ----
        const __half* zw = zt + (tg * 32) * ZP;
        const __half* bw = (const __half*)(smem + SM_CB + (st & 1) * CB_BYTES) + (ch * 32) * ZP;

        float4 acc[2][4];
#pragma unroll
        for (int mi = 0; mi < 2; ++mi)
#pragma unroll
            for (int nj = 0; nj < 4; ++nj) acc[mi][nj] = make_float4(0.f, 0.f, 0.f, 0.f);

#pragma unroll 4
        for (int ks = 0; ks < 16; ++ks) {
            int kb = ks * 16;
            uint32_t A[2][4], B[4][2];
#pragma unroll
            for (int mi = 0; mi < 2; ++mi) {
                const __half* zr = zw + (mi * 16 + r) * ZP + kb + c2;
                A[mi][0] = *(const uint32_t*)(zr);
                A[mi][1] = *(const uint32_t*)(zr + 8 * ZP);
                A[mi][2] = *(const uint32_t*)(zr + 8);
                A[mi][3] = *(const uint32_t*)(zr + 8 * ZP + 8);
            }
#pragma unroll
            for (int nj = 0; nj < 4; ++nj) {
                const __half* br = bw + (nj * 8 + r) * ZP + kb + c2;
                B[nj][0] = *(const uint32_t*)(br);
                B[nj][1] = *(const uint32_t*)(br + 8);
            }
#pragma unroll
            for (int mi = 0; mi < 2; ++mi)
#pragma unroll
                for (int nj = 0; nj < 4; ++nj)
                    mma16816(acc[mi][nj], A[mi], B[nj]);
        }

        // ---- epilogue: scores + per-thread top-3 per owned token slot ----
        int jbase = st * SCODES + ch * 32 + c2;
#pragma unroll
        for (int nj = 0; nj < 4; ++nj) {
            int j = jbase + nj * 8;
            float cn0 = cns[j], cn1 = cns[j + 1];
#pragma unroll
            for (int mi = 0; mi < 2; ++mi) {
                float4 c = acc[mi][nj];
                ins3(cn0 - 2.f * c.x, j,     bv[mi * 2],     bi[mi * 2]);
                ins3(cn1 - 2.f * c.y, j + 1, bv[mi * 2],     bi[mi * 2]);
                ins3(cn0 - 2.f * c.z, j,     bv[mi * 2 + 1], bi[mi * 2 + 1]);
                ins3(cn1 - 2.f * c.w, j + 1, bv[mi * 2 + 1], bi[mi * 2 + 1]);
            }
        }

        CP_WAIT0();
        __syncthreads();
    }

    // ---- per-token global min (8 owner threads per token) ----
#pragma unroll
    for (int s = 0; s < 4; ++s) {
        int tokl = tg * 32 + (s >> 1) * 16 + (s & 1) * 8 + r;
        atomicMin(&minkey[tokl], fenc(bv[s][0]));
    }
    __syncthreads();

    // ---- append margin candidates ----
#pragma unroll
    for (int s = 0; s < 4; ++s) {
        int tokl = tg * 32 + (s >> 1) * 16 + (s & 1) * 8 + r;
        float thr = fdec(minkey[tokl]) + MARGIN;
#pragma unroll
        for (int q = 0; q < 3; ++q) {
            if (bv[s][q] <= thr) {
                int pos = atomicAdd(&candcnt[tokl], 1);
                if (pos < MAXCAND) cand[tokl * MAXCAND + pos] = bi[s][q];
            }
        }
    }
    __syncthreads();

    // ---- resolve: one thread per token; exact rescore when ambiguous ----
    if (tid < MT) {
        int tok = tid;
        int cnt = candcnt[tok]; if (cnt > MAXCAND) cnt = MAXCAND;
        int best = cand[tok * MAXCAND];
        if (cnt > 1) {
            const float* zp = zbase + tok;
            float zn = 0.f;
#pragma unroll 8
            for (int k = 0; k < CDIM; ++k) {
                float v = zp[(size_t)k * SP];
                zn = __fadd_rn(zn, __fmul_rn(v, v));
            }
            float bsc = 3.4e38f; best = 0x7fffffff;
            for (int q = 0; q < cnt; ++q) {
                int j = cand[tok * MAXCAND + q];
                const float* cr = cb + (size_t)j * CDIM;
                float acc = 0.f;
#pragma unroll 8
                for (int k = 0; k < CDIM; ++k)
                    acc = __fmaf_rn(zp[(size_t)k * SP], cr[k], acc);
                float sc = __fadd_rn(__fadd_rn(zn, __fmul_rn(acc, -2.f)), cns[j]);
                if (sc < bsc || (sc == bsc && j < best)) { bsc = sc; best = j; }
            }
        }
        int n = n0 + tok;
        g_idx[n] = best;
        if (oidx) oidx[n] = (float)best;
    }
}

// ---------------------------------------------------------------------------
// gather + transpose writer: 32 tokens x 256 ch per block (~34KB smem)
// ---------------------------------------------------------------------------
#define WT 32
#define WP 33
__global__ __launch_bounds__(256) void write_kernel(
    const float* __restrict__ cb, const float* __restrict__ z,
    float* __restrict__ outq, float* __restrict__ outst)
{
    __shared__ float tile[CDIM * WP];
    __shared__ int   sidx[WT];

    const int tid = threadIdx.x;
    const int n0  = blockIdx.x * WT;
    const int b   = n0 / SP, s0 = n0 % SP;

    if (tid < WT) sidx[tid] = g_idx[n0 + tid];
    __syncthreads();

    const int c = tid;
#pragma unroll 8
    for (int tok = 0; tok < WT; ++tok)
        tile[c * WP + tok] = cb[(size_t)sidx[tok] * CDIM + c];
    __syncthreads();

    const size_t base = (size_t)b * CDIM * SP + s0;
#pragma unroll 4
    for (int rr = 0; rr < WT; ++rr) {
        int lin = rr * 256 + tid;
        int cc = lin >> 5, tok = lin & 31;
        size_t addr = base + (size_t)cc * SP + tok;
        float q = tile[cc * WP + tok];
        outq[addr] = q;
        if (outst) {
            float zv = z[addr];
            outst[addr] = __fadd_rn(zv, __fadd_rn(q, -zv));
        }
    }
}

// ---------------------------------------------------------------------------
extern "C" void kernel_launch(void* const* d_in, const int* in_sizes, int n_in,
                              void* d_out, int out_size) {
    const float* z  = (const float*)d_in[0];
    const float* cb = (const float*)d_in[1];
    float* out = (float*)d_out;

    float* outq   = out;
    float* outst  = nullptr;
    float* outidx = nullptr;
    if (out_size >= 2 * NQ + NTOK)      { outst = out + NQ; outidx = out + 2 * (size_t)NQ; }
    else if (out_size >= 2 * NQ)        { outst = out + NQ; }
    else if (out_size >= NQ + NTOK)     { outidx = out + NQ; }

    cudaFuncSetAttribute(screen_kernel, cudaFuncAttributeMaxDynamicSharedMemorySize, SM_TOTAL);

    cnorm_kernel<<<NCODE / 256, 256>>>(cb);
    cbh_kernel<<<NCODE * CDIM / 256, 256>>>(cb);
    screen_kernel<<<NTOK / MT, 256, SM_TOTAL>>>(z, cb, outidx);
    write_kernel<<<NTOK / WT, 256>>>(cb, z, outq, outst);
}